// round 4
// baseline (speedup 1.0000x reference)
#include <cuda_runtime.h>

// ---------------------------------------------------------------------------
// Model_38225208935040: multi-region perturbed PINN forward.
//
// Algebraic collapse: mean over each symmetric perturbation grid of
// wave(base + delta) = Cd * wave(base), with
//   Cd_j = prod_d [ (1/s) * sum_i cos(lin_i * W1[d, j]) ]
// (sin-mean vanishes on a symmetric grid; grid mean factorizes per dim).
// So 496 embedding evals/point -> 1 wave(base) + 3 precomputed 64-vectors.
//
// R4: occupancy push. launch_bounds(256,3), per-column mixer (fewer temps),
// Cd computed per-block in shared (no setup kernel), 2 barriers per layer.
// ---------------------------------------------------------------------------

#define PPB 8          // points per block
#define NTHREADS 256
#define EPAD 260       // esh row stride (bank-conflict padding)
#define HPAD 68        // hsh row stride

// -------------------------- main fused kernel ------------------------------
__global__ void __launch_bounds__(NTHREADS, 3) model_main_kernel(
    const float* __restrict__ x, const float* __restrict__ y, const float* __restrict__ t,
    const float* __restrict__ W1, const float* __restrict__ b1,
    const float* __restrict__ pwa, const float* __restrict__ pwb,
    const float* __restrict__ W2, const float* __restrict__ b2,
    const float* __restrict__ mW1, const float* __restrict__ mb1,
    const float* __restrict__ pmwa, const float* __restrict__ pmwb,
    const float* __restrict__ mW2, const float* __restrict__ pmb2,
    const float* __restrict__ W0, const float* __restrict__ b0,
    const float* __restrict__ pwa0, const float* __restrict__ pwb0,
    const float* __restrict__ Wh, const float* __restrict__ bh,
    const float* __restrict__ wah, const float* __restrict__ wbh,
    const float* __restrict__ Wf1, const float* __restrict__ bf1,
    const float* __restrict__ pwaf, const float* __restrict__ pwbf,
    const float* __restrict__ Wf2, const float* __restrict__ bf2,
    float* __restrict__ out, int npts)
{
    __shared__ float  cdsh[3][64];         // per-region Cd vectors
    __shared__ float4 swc[PPB][64];        // (w, Cd1*w, Cd2*w, Cd3*w)
    __shared__ float  esh[PPB][EPAD];      // mixed features e (padded rows)
    __shared__ float  hsh[PPB][HPAD];      // out-MLP hidden state (padded)
    __shared__ float4 pshare[4][PPB][16];  // split-K partials [group][pt][f-quad]

    const int tid = threadIdx.x;
    const int base_pt = blockIdx.x * PPB;

    // ---------------- Phase A0: Cd for this block's use --------------------
    if (tid < 192) {
        int r = tid >> 6;
        int j = tid & 63;
        const int   S[3] = {3, 5, 7};
        const float R[3] = {0.01f, 0.05f, 0.09f};
        int s = S[r];
        float rr = R[r];
        float inv = 1.0f / (float)s;
        float step = 2.0f * rr / (float)(s - 1);
        float prod = 1.0f;
        #pragma unroll
        for (int d = 0; d < 3; d++) {
            float w = W1[d * 64 + j];
            float c = 1.0f;                      // center sample (lin = 0)
            for (int i = 0; i < (s >> 1); i++)   // symmetric pairs
                c += 2.0f * __cosf((step * (float)i - rr) * w);
            prod *= c * inv;
        }
        cdsh[r][j] = prod;
    }
    __syncthreads();

    // ---------------- Phase A: base embedding pre-activation ---------------
    {
        const float wa = pwa[0], wb = pwb[0];
        #pragma unroll
        for (int it = 0; it < 2; it++) {
            int i  = tid + it * NTHREADS;
            int pt = i >> 6;
            int j  = i & 63;
            int n  = base_pt + pt;
            if (n >= npts) n = npts - 1;
            float xv = x[n], yv = y[n], tv = t[n];
            float z = fmaf(xv, W1[j], fmaf(yv, W1[64 + j], fmaf(tv, W1[128 + j], b1[j])));
            float sn, cn;
            __sincosf(z, &sn, &cn);
            float w = fmaf(wa, sn, wb * cn);
            swc[pt][j] = make_float4(w, cdsh[0][j] * w, cdsh[1][j] * w, cdsh[2][j] * w);
        }
    }
    __syncthreads();

    // ---------------- Phase B: 4-region GEMV vs W2 [64,256] ----------------
    // Thread owns column quad q for TWO points (pg, pg+4); each weight
    // float4 load feeds 32 FMAs.
    {
        const int q  = tid & 63;
        const int pg = tid >> 6;             // warp-uniform point group
        const float4* __restrict__ W2v = (const float4*)W2;   // [64][64] float4
        float4 a[2][4];                      // [pt][col]; components = regions
        #pragma unroll
        for (int p = 0; p < 2; p++)
            #pragma unroll
            for (int c = 0; c < 4; c++)
                a[p][c] = make_float4(0.f, 0.f, 0.f, 0.f);

        #pragma unroll 8
        for (int j = 0; j < 64; j++) {
            float4 w  = W2v[j * 64 + q];     // coalesced LDG.128
            float4 c0 = swc[pg][j];          // broadcast LDS.128
            float4 c1 = swc[pg + 4][j];
            a[0][0].x = fmaf(c0.x, w.x, a[0][0].x); a[0][0].y = fmaf(c0.y, w.x, a[0][0].y);
            a[0][0].z = fmaf(c0.z, w.x, a[0][0].z); a[0][0].w = fmaf(c0.w, w.x, a[0][0].w);
            a[0][1].x = fmaf(c0.x, w.y, a[0][1].x); a[0][1].y = fmaf(c0.y, w.y, a[0][1].y);
            a[0][1].z = fmaf(c0.z, w.y, a[0][1].z); a[0][1].w = fmaf(c0.w, w.y, a[0][1].w);
            a[0][2].x = fmaf(c0.x, w.z, a[0][2].x); a[0][2].y = fmaf(c0.y, w.z, a[0][2].y);
            a[0][2].z = fmaf(c0.z, w.z, a[0][2].z); a[0][2].w = fmaf(c0.w, w.z, a[0][2].w);
            a[0][3].x = fmaf(c0.x, w.w, a[0][3].x); a[0][3].y = fmaf(c0.y, w.w, a[0][3].y);
            a[0][3].z = fmaf(c0.z, w.w, a[0][3].z); a[0][3].w = fmaf(c0.w, w.w, a[0][3].w);
            a[1][0].x = fmaf(c1.x, w.x, a[1][0].x); a[1][0].y = fmaf(c1.y, w.x, a[1][0].y);
            a[1][0].z = fmaf(c1.z, w.x, a[1][0].z); a[1][0].w = fmaf(c1.w, w.x, a[1][0].w);
            a[1][1].x = fmaf(c1.x, w.y, a[1][1].x); a[1][1].y = fmaf(c1.y, w.y, a[1][1].y);
            a[1][1].z = fmaf(c1.z, w.y, a[1][1].z); a[1][1].w = fmaf(c1.w, w.y, a[1][1].w);
            a[1][2].x = fmaf(c1.x, w.z, a[1][2].x); a[1][2].y = fmaf(c1.y, w.z, a[1][2].y);
            a[1][2].z = fmaf(c1.z, w.z, a[1][2].z); a[1][2].w = fmaf(c1.w, w.z, a[1][2].w);
            a[1][3].x = fmaf(c1.x, w.w, a[1][3].x); a[1][3].y = fmaf(c1.y, w.w, a[1][3].y);
            a[1][3].z = fmaf(c1.z, w.w, a[1][3].z); a[1][3].w = fmaf(c1.w, w.w, a[1][3].w);
        }

        // ------------- Phase C: mixer (4 -> 8 -> 1), per column ------------
        const float4 b2q = ((const float4*)b2)[q];
        const float mwa = pmwa[0], mwb = pmwb[0], mb2v = pmb2[0];
        #pragma unroll
        for (int c = 0; c < 4; c++) {
            float bc = (c == 0) ? b2q.x : (c == 1) ? b2q.y : (c == 2) ? b2q.z : b2q.w;
            // region sums for this column, both points (2 ILP chains)
            float s00 = a[0][c].x + bc, s01 = a[0][c].y + bc,
                  s02 = a[0][c].z + bc, s03 = a[0][c].w + bc;
            float s10 = a[1][c].x + bc, s11 = a[1][c].y + bc,
                  s12 = a[1][c].z + bc, s13 = a[1][c].w + bc;
            float e0 = mb2v, e1 = mb2v;
            #pragma unroll
            for (int h = 0; h < 8; h++) {
                float w0 = mW1[h], w1 = mW1[8 + h], w2 = mW1[16 + h], w3 = mW1[24 + h];
                float bb = mb1[h], m2 = mW2[h];
                float z0 = fmaf(s00, w0, fmaf(s01, w1, fmaf(s02, w2, fmaf(s03, w3, bb))));
                float z1 = fmaf(s10, w0, fmaf(s11, w1, fmaf(s12, w2, fmaf(s13, w3, bb))));
                float sn, cn;
                __sincosf(z0, &sn, &cn); e0 = fmaf(fmaf(mwa, sn, mwb * cn), m2, e0);
                __sincosf(z1, &sn, &cn); e1 = fmaf(fmaf(mwa, sn, mwb * cn), m2, e1);
            }
            esh[pg][4 * q + c]     = e0;
            esh[pg + 4][4 * q + c] = e1;
        }
    }
    __syncthreads();

    // ---------------- Phase D: out MLP, split-K + 2 pts/thread -------------
    const int f4 = tid & 15;           // feature quad
    const int pp = (tid >> 4) & 3;     // points pp and pp+4
    const int g  = tid >> 6;           // k-group
    const float* ps = (const float*)pshare;   // flat [g][pt][64]

    // layer 0: 256 -> 64 (k split 4 x 64)
    {
        const float4* __restrict__ W0v = (const float4*)W0;  // [256][16] float4
        float4 acc0 = {0,0,0,0}, acc1 = {0,0,0,0};
        #pragma unroll 8
        for (int kk = 0; kk < 64; kk++) {
            int k = g * 64 + kk;
            float4 w = W0v[k * 16 + f4];
            float e0 = esh[pp][k];
            float e1 = esh[pp + 4][k];
            acc0.x = fmaf(e0, w.x, acc0.x); acc0.y = fmaf(e0, w.y, acc0.y);
            acc0.z = fmaf(e0, w.z, acc0.z); acc0.w = fmaf(e0, w.w, acc0.w);
            acc1.x = fmaf(e1, w.x, acc1.x); acc1.y = fmaf(e1, w.y, acc1.y);
            acc1.z = fmaf(e1, w.z, acc1.z); acc1.w = fmaf(e1, w.w, acc1.w);
        }
        pshare[g][pp][f4]     = acc0;
        pshare[g][pp + 4][f4] = acc1;
        __syncthreads();
        const float lwa = pwa0[0], lwb = pwb0[0];
        #pragma unroll
        for (int it = 0; it < 2; it++) {
            int i = tid + it * NTHREADS;
            int ptR = i >> 6, f = i & 63;
            float a = b0[f] + (ps[(0 * PPB + ptR) * 64 + f] + ps[(1 * PPB + ptR) * 64 + f])
                            + (ps[(2 * PPB + ptR) * 64 + f] + ps[(3 * PPB + ptR) * 64 + f]);
            float sn, cn;
            __sincosf(a, &sn, &cn);
            hsh[ptR][f] = fmaf(lwa, sn, lwb * cn);
        }
        __syncthreads();
    }

    // 3 hidden layers + final hidden: 64 -> 64 with wave (k split 4 x 16)
    #pragma unroll 1
    for (int L = 0; L < 4; L++) {
        const float* __restrict__ Wl = (L < 3) ? (Wh + L * 4096) : Wf1;
        const float* __restrict__ bl = (L < 3) ? (bh + L * 64)   : bf1;
        const float  lwa = (L < 3) ? wah[L] : pwaf[0];
        const float  lwb = (L < 3) ? wbh[L] : pwbf[0];
        const float4* __restrict__ Wv = (const float4*)Wl;   // [64][16] float4
        float4 acc0 = {0,0,0,0}, acc1 = {0,0,0,0};
        #pragma unroll
        for (int kk = 0; kk < 16; kk++) {
            int k = g * 16 + kk;
            float4 w = Wv[k * 16 + f4];
            float h0 = hsh[pp][k];
            float h1 = hsh[pp + 4][k];
            acc0.x = fmaf(h0, w.x, acc0.x); acc0.y = fmaf(h0, w.y, acc0.y);
            acc0.z = fmaf(h0, w.z, acc0.z); acc0.w = fmaf(h0, w.w, acc0.w);
            acc1.x = fmaf(h1, w.x, acc1.x); acc1.y = fmaf(h1, w.y, acc1.y);
            acc1.z = fmaf(h1, w.z, acc1.z); acc1.w = fmaf(h1, w.w, acc1.w);
        }
        pshare[g][pp][f4]     = acc0;
        pshare[g][pp + 4][f4] = acc1;
        __syncthreads();               // partials visible; all hsh reads done
        #pragma unroll
        for (int it = 0; it < 2; it++) {
            int i = tid + it * NTHREADS;
            int ptR = i >> 6, f = i & 63;
            float a = bl[f] + (ps[(0 * PPB + ptR) * 64 + f] + ps[(1 * PPB + ptR) * 64 + f])
                            + (ps[(2 * PPB + ptR) * 64 + f] + ps[(3 * PPB + ptR) * 64 + f]);
            float sn, cn;
            __sincosf(a, &sn, &cn);
            hsh[ptR][f] = fmaf(lwa, sn, lwb * cn);   // safe: reads done pre-barrier
        }
        __syncthreads();               // hsh writes visible for next layer
    }

    // output: 64 -> 3
    if (tid < PPB * 3) {
        int pt = tid / 3, f = tid % 3;
        int n = base_pt + pt;
        if (n < npts) {
            float a0 = 0.f, a1 = 0.f, a2 = 0.f, a3 = 0.f;
            #pragma unroll
            for (int i = 0; i < 16; i++) {
                a0 = fmaf(hsh[pt][4 * i + 0], Wf2[(4 * i + 0) * 3 + f], a0);
                a1 = fmaf(hsh[pt][4 * i + 1], Wf2[(4 * i + 1) * 3 + f], a1);
                a2 = fmaf(hsh[pt][4 * i + 2], Wf2[(4 * i + 2) * 3 + f], a2);
                a3 = fmaf(hsh[pt][4 * i + 3], Wf2[(4 * i + 3) * 3 + f], a3);
            }
            out[n * 3 + f] = bf2[f] + (a0 + a1) + (a2 + a3);
        }
    }
}

// ---------------------------------------------------------------------------
extern "C" void kernel_launch(void* const* d_in, const int* in_sizes, int n_in,
                              void* d_out, int out_size) {
    const float* x    = (const float*)d_in[0];
    const float* y    = (const float*)d_in[1];
    const float* t    = (const float*)d_in[2];
    const float* W1   = (const float*)d_in[3];
    const float* b1   = (const float*)d_in[4];
    const float* wa   = (const float*)d_in[5];
    const float* wb   = (const float*)d_in[6];
    const float* W2   = (const float*)d_in[7];
    const float* b2   = (const float*)d_in[8];
    const float* mW1  = (const float*)d_in[9];
    const float* mb1  = (const float*)d_in[10];
    const float* mwa  = (const float*)d_in[11];
    const float* mwb  = (const float*)d_in[12];
    const float* mW2  = (const float*)d_in[13];
    const float* mb2  = (const float*)d_in[14];
    const float* W0   = (const float*)d_in[15];
    const float* b0   = (const float*)d_in[16];
    const float* wa0  = (const float*)d_in[17];
    const float* wb0  = (const float*)d_in[18];
    const float* Wh   = (const float*)d_in[19];
    const float* bh   = (const float*)d_in[20];
    const float* wah  = (const float*)d_in[21];
    const float* wbh  = (const float*)d_in[22];
    const float* Wf1  = (const float*)d_in[23];
    const float* bf1  = (const float*)d_in[24];
    const float* waf  = (const float*)d_in[25];
    const float* wbf  = (const float*)d_in[26];
    const float* Wf2  = (const float*)d_in[27];
    const float* bf2  = (const float*)d_in[28];
    float* out = (float*)d_out;

    int npts = in_sizes[0];
    int nblocks = (npts + PPB - 1) / PPB;

    model_main_kernel<<<nblocks, NTHREADS>>>(
        x, y, t, W1, b1, wa, wb, W2, b2,
        mW1, mb1, mwa, mwb, mW2, mb2,
        W0, b0, wa0, wb0, Wh, bh, wah, wbh,
        Wf1, bf1, waf, wbf, Wf2, bf2,
        out, npts);
}